// round 14
// baseline (speedup 1.0000x reference)
#include <cuda_runtime.h>
#include <cuda_fp16.h>
#include <cstdint>

// ============================================================================
// SimpleMACELayer — Round 13: K=64 chunks (no h-half split), EPB=32,
// direct-LDG B-fragments from frag-permuted g_Mb (no sM staging).
// fp16 mma.sync m16n8k16, q-split warps, 4 CTAs/SM.
// ============================================================================

#define EPB 32
#define NTHREADS 256
#define Q_TOTAL 99

__constant__ signed char cQP[Q_TOTAL] = {
    0, 1,1,1, 2,2,2,2,2, 3,3,3,3,3,3,3,
    4,4,4, 5, 6,6,6,6,6, 7,7,7, 8,8,8,8,8,8,8, 9,9,9,9,9,
    10,10,10,10,10, 11,11,11, 12,12,12,12,12,12,12, 13,
    14,14,14,14,14, 15,15,15, 16,16,16,16,16,16,16,
    17,17,17,17,17,17,17, 18,18,18,18,18, 19,19,19,
    20,20,20,20,20,20,20, 21, 22,22,22,22,22};
__constant__ signed char cQKG[Q_TOTAL] = {
    0, 1,2,3, 4,5,6,7,8, 9,10,11,12,13,14,15,
    1,2,3, 0, 4,5,6,7,8, 1,2,3, 9,10,11,12,13,14,15, 4,5,6,7,8,
    4,5,6,7,8, 1,2,3, 9,10,11,12,13,14,15, 0,
    4,5,6,7,8, 1,2,3, 9,10,11,12,13,14,15,
    9,10,11,12,13,14,15, 4,5,6,7,8, 1,2,3,
    9,10,11,12,13,14,15, 0, 4,5,6,7,8};
__constant__ signed char cQJ0[Q_TOTAL] = {
    0, 1,1,1, 4,4,4,4,4, 9,9,9,9,9,9,9,
    0,0,0, 1, 1,1,1,1,1, 4,4,4, 4,4,4,4,4,4,4, 9,9,9,9,9,
    0,0,0,0,0, 1,1,1, 1,1,1,1,1,1,1, 4,
    4,4,4,4,4, 9,9,9, 9,9,9,9,9,9,9,
    0,0,0,0,0,0,0, 1,1,1,1,1, 4,4,4,
    4,4,4,4,4,4,4, 9, 9,9,9,9,9};
__constant__ int cPSTART[5] = {0, 16, 40, 71, 99};

// Fused weights, fp16, B-fragment-permuted:
// g_Mb[q*4096 + o'*64 + ks*16 + slot], slot order per 16-k block:
// (k0,k0+1,k0+8,k0+9) for tig -> lane LDG.64 gives (b0,b1) directly.
__device__ __half g_Mb[Q_TOTAL * 4096];

__device__ __forceinline__ void mma16(float* c, const uint32_t* a,
                                      uint32_t b0, uint32_t b1) {
    asm volatile(
        "mma.sync.aligned.m16n8k16.row.col.f32.f16.f16.f32 "
        "{%0,%1,%2,%3}, {%4,%5,%6,%7}, {%8,%9}, {%0,%1,%2,%3};"
        : "+f"(c[0]), "+f"(c[1]), "+f"(c[2]), "+f"(c[3])
        : "r"(a[0]), "r"(a[1]), "r"(a[2]), "r"(a[3]), "r"(b0), "r"(b1));
}
__device__ __forceinline__ void ldmx4(uint32_t* r, uint32_t addr) {
    asm volatile(
        "ldmatrix.sync.aligned.m8n8.x4.shared.b16 {%0,%1,%2,%3}, [%4];"
        : "=r"(r[0]), "=r"(r[1]), "=r"(r[2]), "=r"(r[3]) : "r"(addr));
}
__device__ __forceinline__ uint32_t smem_u32(const void* p) {
    uint32_t a;
    asm("{ .reg .u64 t; cvta.to.shared.u64 t, %1; cvt.u32.u64 %0, t; }"
        : "=r"(a) : "l"(p));
    return a;
}

// ---------------------------------------------------------------------------
__global__ void build_M_kernel(const float* __restrict__ tw,
                               const float* __restrict__ wlin) {
    int q = blockIdx.x, p = cQP[q], kg = cQKG[q];
    __shared__ float twS[4096], wlS[4096];
    for (int i = threadIdx.x; i < 4096; i += blockDim.x) twS[i] = tw[p * 4096 + i];
    for (int i = threadIdx.x; i < 4096; i += blockDim.x) {
        int o = i >> 6, op = i & 63;
        wlS[o * 64 + op] = wlin[op * 1024 + o * 16 + kg];
    }
    __syncthreads();
    for (int r = threadIdx.x; r < 4096; r += blockDim.x) {
        int h = r >> 6, op = r & 63;   // h = K index, op = o'
        float acc = 0.0f;
#pragma unroll 8
        for (int o = 0; o < 64; ++o) acc += twS[h * 64 + o] * wlS[o * 64 + op];
        // fragment-permuted slot within the 16-k block
        int ks = h >> 4, rr = h & 15;
        int slot = (rr < 8) ? ((rr >> 1) * 4 + (rr & 1))
                            : (((rr & 7) >> 1) * 4 + 2 + (rr & 1));
        g_Mb[q * 4096 + op * 64 + ks * 16 + slot] = __float2half_rn(acc);
    }
}

__global__ void init_out_kernel(float* __restrict__ out,
                                const float* __restrict__ b, int total) {
    int i = blockIdx.x * blockDim.x + threadIdx.x;
    if (i < total) out[i] = b[i & 63];
}

// ---------------------------------------------------------------------------
// SMEM layout (bytes), EPB=32:
//   sSrc half [ic7][e32][h64]          0     28672  (reused as sRed 8KB)
//   sU   half [q2][e32][72]        28672      9216  (row 144B, +4 banks/row)
//   sY   f32  [j16][e32]           37888      2048
//   sAI  f32  [ic7][e32][q2]       39936      1792
//   sIdx i32  [2][32]              41728       256
// total 41984 B -> 4 CTAs/SM (167936 <= 233472)
#define U_OFF   28672
#define Y_OFF   37888
#define A_OFF   39936
#define IDX_OFF 41728
#define SMEM_TOTAL 41984

#define U_STRIDE 72                 // halves (144 B rows)
#define U_QSZ (EPB * U_STRIDE)      // 2304 halves = 4608 B

__global__ __launch_bounds__(NTHREADS, 4)
void edge_kernel(const float* __restrict__ nf, const float* __restrict__ ev,
                 const int* __restrict__ ei, const float* __restrict__ cg,
                 float* __restrict__ out, int E) {
    extern __shared__ char smx[];
    __half* sSrc = (__half*)smx;
    __half* sU = (__half*)(smx + U_OFF);
    float* sY = (float*)(smx + Y_OFF);
    float* sAI = (float*)(smx + A_OFF);   // interleaved [ic][e][q0,q1]
    int* sIdx = (int*)(smx + IDX_OFF);
    const int tid = threadIdx.x;
    const int e0 = blockIdx.x * EPB;
    const uint32_t sb = smem_u32(smx);

    // ---- Y + indices ----
    if (tid < EPB) {
        int e = e0 + tid;
        if (e < E) {
            float x = ev[e * 3], y = ev[e * 3 + 1], z = ev[e * 3 + 2];
            float x2 = x * x, y2 = y * y, z2 = z * z;
            float Y[16];
            Y[0] = 0.28209479177387814f;
            Y[1] = 0.4886025119029199f * y;
            Y[2] = 0.4886025119029199f * z;
            Y[3] = 0.4886025119029199f * x;
            Y[4] = 1.0925484305920792f * x * y;
            Y[5] = 1.0925484305920792f * y * z;
            Y[6] = 0.31539156525252005f * (3.0f * z2 - 1.0f);
            Y[7] = 1.0925484305920792f * x * z;
            Y[8] = 0.5462742152960396f * (x2 - y2);
            Y[9] = 0.5900435899266435f * y * (3.0f * x2 - y2);
            Y[10] = 2.890611442640554f * x * y * z;
            Y[11] = 0.4570457994644658f * y * (5.0f * z2 - 1.0f);
            Y[12] = 0.3731763325901154f * z * (5.0f * z2 - 3.0f);
            Y[13] = 0.4570457994644658f * x * (5.0f * z2 - 1.0f);
            Y[14] = 1.445305721320277f * z * (x2 - y2);
            Y[15] = 0.5900435899266435f * x * (x2 - 3.0f * y2);
#pragma unroll
            for (int j = 0; j < 16; ++j) sY[j * EPB + tid] = Y[j];
            sIdx[tid] = ei[e];
            sIdx[EPB + tid] = ei[E + e];
        } else {
#pragma unroll
            for (int j = 0; j < 16; ++j) sY[j * EPB + tid] = 0.0f;
            sIdx[tid] = 0;
            sIdx[EPB + tid] = -1;
        }
    }

    // q-split warp mapping: warp = (qq, wx, wy2); warp tile 16e x 32o', K=64
    const int lane = tid & 31, gid = lane >> 2, tig = lane & 3;
    const int wid = tid >> 5;
    const int qq = wid & 1;
    const int wx = (wid >> 1) & 1;
    const int wy2 = wid >> 2;
    float acc[4][4];
#pragma unroll
    for (int nt = 0; nt < 4; ++nt)
#pragma unroll
        for (int r = 0; r < 4; ++r) acc[nt][r] = 0.0f;

    // ldmatrix A-frag base: rows wy2*16 + (lane&15), quadrant (lane>>4)*16B
    const uint32_t aFragBase = sb + U_OFF + qq * 4608 +
        (uint32_t)((wy2 * 16 + (lane & 15)) * 144 + (lane >> 4) * 16);
    // B-frag global base offset (per lane): row o' = wx*32 + nt*8 + gid
    const __half* bBase = g_Mb + (wx * 32 + gid) * 64 + tig * 4;
    __syncthreads();

    for (int g = 0; g < 4; ++g) {
        const int nc = 2 * g + 1, i0 = g * g;
        // ---- gather sSrc[ic][e][h] for all 64 h (once per g) ----
        for (int idx = tid; idx < EPB * 64; idx += NTHREADS) {
            int e = idx >> 6, hh = idx & 63;
            const float* base = nf + (size_t)sIdx[e] * 1024 + hh * 16;
            __half* d = sSrc + e * 64 + hh;  // + ic*2048
            if (g == 0) {
                d[0] = __float2half_rn(__ldg(base));
            } else if (g == 1) {
                float4 v = __ldg((const float4*)base);
                d[0] = __float2half_rn(v.y);
                d[2048] = __float2half_rn(v.z);
                d[4096] = __float2half_rn(v.w);
            } else if (g == 2) {
                float4 v = __ldg((const float4*)(base + 4));
                float s = __ldg(base + 8);
                d[0] = __float2half_rn(v.x);
                d[2048] = __float2half_rn(v.y);
                d[4096] = __float2half_rn(v.z);
                d[6144] = __float2half_rn(v.w);
                d[8192] = __float2half_rn(s);
            } else {
                float4 va = __ldg((const float4*)(base + 8));
                float4 vb = __ldg((const float4*)(base + 12));
                d[0] = __float2half_rn(va.y);
                d[2048] = __float2half_rn(va.z);
                d[4096] = __float2half_rn(va.w);
                d[6144] = __float2half_rn(vb.x);
                d[8192] = __float2half_rn(vb.y);
                d[10240] = __float2half_rn(vb.z);
                d[12288] = __float2half_rn(vb.w);
            }
        }
        __syncthreads();

        const int qend = cPSTART[g + 1];
        for (int qb = cPSTART[g]; qb < qend; qb += 2) {
            const int nqc = (qend - qb >= 2) ? 2 : 1;

            // ---- phase A: A-coeffs -> interleaved sAI (once per q!) ----
            for (int idx = tid; idx < nqc * nc * EPB; idx += NTHREADS) {
                int e = idx & 31, r = idx >> 5;
                int ic = r % nc, qi = r / nc, q = qb + qi;
                int j0 = cQJ0[q], kg = cQKG[q];
                int nj = (j0 == 0) ? 1 : (j0 == 1) ? 3 : (j0 == 4) ? 5 : 7;
                const float* cgp = cg + (i0 + ic) * 256 + j0 * 16 + kg;
                float a = 0.0f;
#pragma unroll
                for (int jc = 0; jc < 7; ++jc)
                    if (jc < nj) a += sY[(j0 + jc) * EPB + e] * __ldg(cgp + jc * 16);
                sAI[(ic * EPB + e) * 2 + qi] = a;
            }
            __syncthreads();

            // ---- phase B: U tiles [q][32e][64h] (1 item/thread) ----
            {
                int e = tid >> 3, hv = tid & 7;   // 8 h's per item
                float u0[8] = {0, 0, 0, 0, 0, 0, 0, 0};
                float u1[8] = {0, 0, 0, 0, 0, 0, 0, 0};
#pragma unroll
                for (int ic = 0; ic < 7; ++ic)
                    if (ic < nc) {
                        uint4 sw = *(const uint4*)(sSrc + ic * 2048 +
                                                   e * 64 + hv * 8);
                        float2 f0 = __half22float2(*(__half2*)&sw.x);
                        float2 f1 = __half22float2(*(__half2*)&sw.y);
                        float2 f2 = __half22float2(*(__half2*)&sw.z);
                        float2 f3 = __half22float2(*(__half2*)&sw.w);
                        float2 a2 = *(const float2*)&sAI[(ic * EPB + e) * 2];
                        u0[0] += a2.x * f0.x; u0[1] += a2.x * f0.y;
                        u0[2] += a2.x * f1.x; u0[3] += a2.x * f1.y;
                        u0[4] += a2.x * f2.x; u0[5] += a2.x * f2.y;
                        u0[6] += a2.x * f3.x; u0[7] += a2.x * f3.y;
                        if (nqc == 2) {
                            u1[0] += a2.y * f0.x; u1[1] += a2.y * f0.y;
                            u1[2] += a2.y * f1.x; u1[3] += a2.y * f1.y;
                            u1[4] += a2.y * f2.x; u1[5] += a2.y * f2.y;
                            u1[6] += a2.y * f3.x; u1[7] += a2.y * f3.y;
                        }
                    }
                {
                    __half2 p0 = __floats2half2_rn(u0[0], u0[1]);
                    __half2 p1 = __floats2half2_rn(u0[2], u0[3]);
                    __half2 p2 = __floats2half2_rn(u0[4], u0[5]);
                    __half2 p3 = __floats2half2_rn(u0[6], u0[7]);
                    uint4 st = {*(uint32_t*)&p0, *(uint32_t*)&p1,
                                *(uint32_t*)&p2, *(uint32_t*)&p3};
                    *(uint4*)(sU + e * U_STRIDE + hv * 8) = st;
                }
                if (nqc == 2) {
                    __half2 p0 = __floats2half2_rn(u1[0], u1[1]);
                    __half2 p1 = __floats2half2_rn(u1[2], u1[3]);
                    __half2 p2 = __floats2half2_rn(u1[4], u1[5]);
                    __half2 p3 = __floats2half2_rn(u1[6], u1[7]);
                    uint4 st = {*(uint32_t*)&p0, *(uint32_t*)&p1,
                                *(uint32_t*)&p2, *(uint32_t*)&p3};
                    *(uint4*)(sU + U_QSZ + e * U_STRIDE + hv * 8) = st;
                }
            }
            __syncthreads();

            // ---- mma phase: warp owns ONE q; A via ldmatrix, B via LDG.64 ----
            if (qq < nqc) {
                const __half* bq = bBase + (qb + qq) * 4096;
#pragma unroll
                for (int ks = 0; ks < 4; ++ks) {
                    uint32_t aF[4];
                    ldmx4(aF, aFragBase + ks * 32);
#pragma unroll
                    for (int nt = 0; nt < 4; ++nt) {
                        uint2 b = __ldg((const uint2*)(bq + nt * 512 + ks * 16));
                        mma16(acc[nt], aF, b.x, b.y);
                    }
                }
            }
            __syncthreads();
        }
    }

    // ---- cross-q reduction: qq=1 warps dump acc, qq=0 warps add ----
    {
        float* sRed = (float*)smx;   // 4 tiles x 16x32 f32 = 8KB (sSrc dead)
        float* tile = sRed + (wy2 * 2 + wx) * 512;
        if (qq == 1) {
#pragma unroll
            for (int nt = 0; nt < 4; ++nt)
#pragma unroll
                for (int r = 0; r < 4; ++r) {
                    int row = gid + (r >> 1) * 8;
                    int col = nt * 8 + tig * 2 + (r & 1);
                    tile[row * 32 + col] = acc[nt][r];
                }
        }
        __syncthreads();
        if (qq == 0) {
#pragma unroll
            for (int nt = 0; nt < 4; ++nt)
#pragma unroll
                for (int r = 0; r < 4; ++r) {
                    int row = gid + (r >> 1) * 8;
                    int col = nt * 8 + tig * 2 + (r & 1);
                    acc[nt][r] += tile[row * 32 + col];
                }
            // ---- epilogue: float2 atomics into out[dst] ----
#pragma unroll
            for (int r = 0; r < 2; ++r) {
                int e = wy2 * 16 + gid + r * 8;
                int dst = sIdx[EPB + e];
                if (dst >= 0) {
                    float* op = out + (size_t)dst * 64 + wx * 32 + 2 * tig;
#pragma unroll
                    for (int nt = 0; nt < 4; ++nt) {
                        float2 v = make_float2(acc[nt][r * 2],
                                               acc[nt][r * 2 + 1]);
                        atomicAdd((float2*)(op + nt * 8), v);
                    }
                }
            }
        }
    }
}

// ---------------------------------------------------------------------------
extern "C" void kernel_launch(void* const* d_in, const int* in_sizes, int n_in,
                              void* d_out, int out_size) {
    const float* nf = (const float*)d_in[0];
    const float* ev = (const float*)d_in[1];
    const int* ei = (const int*)d_in[2];
    const float* cg = (const float*)d_in[3];
    const float* tw = (const float*)d_in[4];
    const float* wlin = (const float*)d_in[5];
    const float* bl = (const float*)d_in[6];
    float* out = (float*)d_out;
    const int E = in_sizes[1] / 3;
    const int N = in_sizes[0] / 1024;

    cudaFuncSetAttribute(edge_kernel,
                         cudaFuncAttributeMaxDynamicSharedMemorySize, SMEM_TOTAL);
    build_M_kernel<<<Q_TOTAL, 256>>>(tw, wlin);
    init_out_kernel<<<(N * 64 + 255) / 256, 256>>>(out, bl, N * 64);
    edge_kernel<<<(E + EPB - 1) / EPB, NTHREADS, SMEM_TOTAL>>>(nf, ev, ei, cg, out, E);
}

// round 15
// speedup vs baseline: 1.1489x; 1.1489x over previous
#include <cuda_runtime.h>
#include <cuda_fp16.h>
#include <cstdint>

// ============================================================================
// SimpleMACELayer — Round 14: R12 skeleton (EPB=64, h-half chunks, q-split
// warps, ldmatrix A-frags) + direct-LDG B-fragments (frag-permuted g_Mb,
// no sM staging). fp16 mma.sync m16n8k16, 4 CTAs/SM.
// ============================================================================

#define EPB 64
#define NTHREADS 256
#define Q_TOTAL 99

__constant__ signed char cQP[Q_TOTAL] = {
    0, 1,1,1, 2,2,2,2,2, 3,3,3,3,3,3,3,
    4,4,4, 5, 6,6,6,6,6, 7,7,7, 8,8,8,8,8,8,8, 9,9,9,9,9,
    10,10,10,10,10, 11,11,11, 12,12,12,12,12,12,12, 13,
    14,14,14,14,14, 15,15,15, 16,16,16,16,16,16,16,
    17,17,17,17,17,17,17, 18,18,18,18,18, 19,19,19,
    20,20,20,20,20,20,20, 21, 22,22,22,22,22};
__constant__ signed char cQKG[Q_TOTAL] = {
    0, 1,2,3, 4,5,6,7,8, 9,10,11,12,13,14,15,
    1,2,3, 0, 4,5,6,7,8, 1,2,3, 9,10,11,12,13,14,15, 4,5,6,7,8,
    4,5,6,7,8, 1,2,3, 9,10,11,12,13,14,15, 0,
    4,5,6,7,8, 1,2,3, 9,10,11,12,13,14,15,
    9,10,11,12,13,14,15, 4,5,6,7,8, 1,2,3,
    9,10,11,12,13,14,15, 0, 4,5,6,7,8};
__constant__ signed char cQJ0[Q_TOTAL] = {
    0, 1,1,1, 4,4,4,4,4, 9,9,9,9,9,9,9,
    0,0,0, 1, 1,1,1,1,1, 4,4,4, 4,4,4,4,4,4,4, 9,9,9,9,9,
    0,0,0,0,0, 1,1,1, 1,1,1,1,1,1,1, 4,
    4,4,4,4,4, 9,9,9, 9,9,9,9,9,9,9,
    0,0,0,0,0,0,0, 1,1,1,1,1, 4,4,4,
    4,4,4,4,4,4,4, 9, 9,9,9,9,9};
__constant__ int cPSTART[5] = {0, 16, 40, 71, 99};

// Fused weights, fp16, B-fragment-permuted and hlf-major:
// g_Mb[q*4096 + hlf*2048 + o'*32 + ks*16 + slot]
// slot: within a 16-k block, order (pair p = k/2 within 8-k half, lo/hi half):
//   k<8:  slot = (k>>1)*4 + (k&1)
//   k>=8: slot = ((k&7)>>1)*4 + 2 + (k&1)
// so lane tig reads slots [tig*4 .. tig*4+3] = (k0,k0+1,k0+8,k0+9) = (b0,b1).
__device__ __half g_Mb[Q_TOTAL * 4096];

__device__ __forceinline__ void mma16(float* c, const uint32_t* a,
                                      uint32_t b0, uint32_t b1) {
    asm volatile(
        "mma.sync.aligned.m16n8k16.row.col.f32.f16.f16.f32 "
        "{%0,%1,%2,%3}, {%4,%5,%6,%7}, {%8,%9}, {%0,%1,%2,%3};"
        : "+f"(c[0]), "+f"(c[1]), "+f"(c[2]), "+f"(c[3])
        : "r"(a[0]), "r"(a[1]), "r"(a[2]), "r"(a[3]), "r"(b0), "r"(b1));
}
__device__ __forceinline__ void ldmx4(uint32_t* r, uint32_t addr) {
    asm volatile(
        "ldmatrix.sync.aligned.m8n8.x4.shared.b16 {%0,%1,%2,%3}, [%4];"
        : "=r"(r[0]), "=r"(r[1]), "=r"(r[2]), "=r"(r[3]) : "r"(addr));
}
__device__ __forceinline__ uint32_t smem_u32(const void* p) {
    uint32_t a;
    asm("{ .reg .u64 t; cvta.to.shared.u64 t, %1; cvt.u32.u64 %0, t; }"
        : "=r"(a) : "l"(p));
    return a;
}

// ---------------------------------------------------------------------------
__global__ void build_M_kernel(const float* __restrict__ tw,
                               const float* __restrict__ wlin) {
    int q = blockIdx.x, p = cQP[q], kg = cQKG[q];
    __shared__ float twS[4096], wlS[4096];
    for (int i = threadIdx.x; i < 4096; i += blockDim.x) twS[i] = tw[p * 4096 + i];
    for (int i = threadIdx.x; i < 4096; i += blockDim.x) {
        int o = i >> 6, op = i & 63;
        wlS[o * 64 + op] = wlin[op * 1024 + o * 16 + kg];
    }
    __syncthreads();
    for (int r = threadIdx.x; r < 4096; r += blockDim.x) {
        int h = r >> 6, op = r & 63;   // h = K index (0..63), op = o'
        float acc = 0.0f;
#pragma unroll 8
        for (int o = 0; o < 64; ++o) acc += twS[h * 64 + o] * wlS[o * 64 + op];
        int hlf = h >> 5, rr = h & 31;
        int ks = rr >> 4, r16 = rr & 15;
        int slot = (r16 < 8) ? ((r16 >> 1) * 4 + (r16 & 1))
                             : (((r16 & 7) >> 1) * 4 + 2 + (r16 & 1));
        g_Mb[q * 4096 + hlf * 2048 + op * 32 + ks * 16 + slot] =
            __float2half_rn(acc);
    }
}

__global__ void init_out_kernel(float* __restrict__ out,
                                const float* __restrict__ b, int total) {
    int i = blockIdx.x * blockDim.x + threadIdx.x;
    if (i < total) out[i] = b[i & 63];
}

// ---------------------------------------------------------------------------
// SMEM layout (bytes), EPB=64 (sM removed vs R12):
//   sSrc half [ic7][e64][hh32]         0     28672  (reused as sRed 16KB)
//   sU   half [q2][e64][40]        28672     10240  (row 80B)
//   sY   f32  [j16][e64]           38912      4096
//   sAI  f32  [ic7][e64][q2]       43008      3584
//   sIdx i32  [2][64]              46592       512
// total 47104 B -> 4 CTAs/SM (188416 <= 233472)
#define U_OFF   28672
#define Y_OFF   38912
#define A_OFF   43008
#define IDX_OFF 46592
#define SMEM_TOTAL 47104

#define U_STRIDE 40
#define U_QSZ (EPB * U_STRIDE)   // 2560 halves = 5120 B

__global__ __launch_bounds__(NTHREADS, 4)
void edge_kernel(const float* __restrict__ nf, const float* __restrict__ ev,
                 const int* __restrict__ ei, const float* __restrict__ cg,
                 float* __restrict__ out, int E) {
    extern __shared__ char smx[];
    __half* sSrc = (__half*)smx;
    __half* sU = (__half*)(smx + U_OFF);
    float* sY = (float*)(smx + Y_OFF);
    float* sAI = (float*)(smx + A_OFF);   // interleaved [ic][e][q0,q1]
    int* sIdx = (int*)(smx + IDX_OFF);
    const int tid = threadIdx.x;
    const int e0 = blockIdx.x * EPB;
    const uint32_t sb = smem_u32(smx);

    // ---- Y + indices ----
    if (tid < EPB) {
        int e = e0 + tid;
        if (e < E) {
            float x = ev[e * 3], y = ev[e * 3 + 1], z = ev[e * 3 + 2];
            float x2 = x * x, y2 = y * y, z2 = z * z;
            float Y[16];
            Y[0] = 0.28209479177387814f;
            Y[1] = 0.4886025119029199f * y;
            Y[2] = 0.4886025119029199f * z;
            Y[3] = 0.4886025119029199f * x;
            Y[4] = 1.0925484305920792f * x * y;
            Y[5] = 1.0925484305920792f * y * z;
            Y[6] = 0.31539156525252005f * (3.0f * z2 - 1.0f);
            Y[7] = 1.0925484305920792f * x * z;
            Y[8] = 0.5462742152960396f * (x2 - y2);
            Y[9] = 0.5900435899266435f * y * (3.0f * x2 - y2);
            Y[10] = 2.890611442640554f * x * y * z;
            Y[11] = 0.4570457994644658f * y * (5.0f * z2 - 1.0f);
            Y[12] = 0.3731763325901154f * z * (5.0f * z2 - 3.0f);
            Y[13] = 0.4570457994644658f * x * (5.0f * z2 - 1.0f);
            Y[14] = 1.445305721320277f * z * (x2 - y2);
            Y[15] = 0.5900435899266435f * x * (x2 - 3.0f * y2);
#pragma unroll
            for (int j = 0; j < 16; ++j) sY[j * EPB + tid] = Y[j];
            sIdx[tid] = ei[e];
            sIdx[EPB + tid] = ei[E + e];
        } else {
#pragma unroll
            for (int j = 0; j < 16; ++j) sY[j * EPB + tid] = 0.0f;
            sIdx[tid] = 0;
            sIdx[EPB + tid] = -1;
        }
    }

    // q-split warp mapping: warp = (qq, wx, wy2)
    const int lane = tid & 31, gid = lane >> 2, tig = lane & 3;
    const int wid = tid >> 5;
    const int qq = wid & 1;
    const int wx = (wid >> 1) & 1;
    const int wy2 = wid >> 2;
    float acc[2][4][4];
#pragma unroll
    for (int mt = 0; mt < 2; ++mt)
#pragma unroll
        for (int nt = 0; nt < 4; ++nt)
#pragma unroll
            for (int r = 0; r < 4; ++r) acc[mt][nt][r] = 0.0f;

    // ldmatrix A-frag base (per lane)
    const uint32_t aFragBase = sb + U_OFF + qq * 5120 +
        (uint32_t)((wy2 * 32 + (lane & 15)) * 80 + (lane >> 4) * 16);
    // B-frag global base (per lane): row o' = wx*32 + nt*8 + gid
    const __half* bBase = g_Mb + (wx * 32 + gid) * 32 + tig * 4;
    __syncthreads();

    for (int g = 0; g < 4; ++g) {
        const int nc = 2 * g + 1, i0 = g * g;
        for (int hlf = 0; hlf < 2; ++hlf) {
            // ---- gather sSrc[ic][e][hh] (vectorized over irreps) ----
            for (int idx = tid; idx < EPB * 32; idx += NTHREADS) {
                int e = idx >> 5, hh = idx & 31;
                const float* base =
                    nf + (size_t)sIdx[e] * 1024 + (hlf * 32 + hh) * 16;
                __half* d = sSrc + e * 32 + hh;  // + ic*2048
                if (g == 0) {
                    d[0] = __float2half_rn(__ldg(base));
                } else if (g == 1) {
                    float4 v = __ldg((const float4*)base);
                    d[0] = __float2half_rn(v.y);
                    d[2048] = __float2half_rn(v.z);
                    d[4096] = __float2half_rn(v.w);
                } else if (g == 2) {
                    float4 v = __ldg((const float4*)(base + 4));
                    float s = __ldg(base + 8);
                    d[0] = __float2half_rn(v.x);
                    d[2048] = __float2half_rn(v.y);
                    d[4096] = __float2half_rn(v.z);
                    d[6144] = __float2half_rn(v.w);
                    d[8192] = __float2half_rn(s);
                } else {
                    float4 va = __ldg((const float4*)(base + 8));
                    float4 vb = __ldg((const float4*)(base + 12));
                    d[0] = __float2half_rn(va.y);
                    d[2048] = __float2half_rn(va.z);
                    d[4096] = __float2half_rn(va.w);
                    d[6144] = __float2half_rn(vb.x);
                    d[8192] = __float2half_rn(vb.y);
                    d[10240] = __float2half_rn(vb.z);
                    d[12288] = __float2half_rn(vb.w);
                }
            }
            __syncthreads();

            const int qend = cPSTART[g + 1];
            for (int qb = cPSTART[g]; qb < qend; qb += 2) {
                const int nqc = (qend - qb >= 2) ? 2 : 1;

                // ---- phase A: A-coeffs -> interleaved sAI ----
                for (int idx = tid; idx < nqc * nc * EPB; idx += NTHREADS) {
                    int e = idx & 63, r = idx >> 6;
                    int ic = r % nc, qi = r / nc, q = qb + qi;
                    int j0 = cQJ0[q], kg = cQKG[q];
                    int nj = (j0 == 0) ? 1 : (j0 == 1) ? 3 : (j0 == 4) ? 5 : 7;
                    const float* cgp = cg + (i0 + ic) * 256 + j0 * 16 + kg;
                    float a = 0.0f;
#pragma unroll
                    for (int jc = 0; jc < 7; ++jc)
                        if (jc < nj) a += sY[(j0 + jc) * EPB + e] * __ldg(cgp + jc * 16);
                    sAI[(ic * EPB + e) * 2 + qi] = a;
                }
                __syncthreads();

                // ---- phase B: U tiles (fp32 math, fp16 store) ----
                for (int idx = tid; idx < EPB * 8; idx += NTHREADS) {
                    int e = idx >> 3, hv = idx & 7;
                    float u0[4] = {0, 0, 0, 0}, u1[4] = {0, 0, 0, 0};
#pragma unroll
                    for (int ic = 0; ic < 7; ++ic)
                        if (ic < nc) {
                            uint2 sw = *(const uint2*)(sSrc + ic * 2048 +
                                                       e * 32 + hv * 4);
                            float2 f0 = __half22float2(*(__half2*)&sw.x);
                            float2 f1 = __half22float2(*(__half2*)&sw.y);
                            float2 a2 = *(const float2*)&sAI[(ic * EPB + e) * 2];
                            u0[0] += a2.x * f0.x; u0[1] += a2.x * f0.y;
                            u0[2] += a2.x * f1.x; u0[3] += a2.x * f1.y;
                            if (nqc == 2) {
                                u1[0] += a2.y * f0.x; u1[1] += a2.y * f0.y;
                                u1[2] += a2.y * f1.x; u1[3] += a2.y * f1.y;
                            }
                        }
                    {
                        __half2 p0 = __floats2half2_rn(u0[0], u0[1]);
                        __half2 p1 = __floats2half2_rn(u0[2], u0[3]);
                        uint2 st = {*(uint32_t*)&p0, *(uint32_t*)&p1};
                        *(uint2*)(sU + e * U_STRIDE + hv * 4) = st;
                    }
                    if (nqc == 2) {
                        __half2 p0 = __floats2half2_rn(u1[0], u1[1]);
                        __half2 p1 = __floats2half2_rn(u1[2], u1[3]);
                        uint2 st = {*(uint32_t*)&p0, *(uint32_t*)&p1};
                        *(uint2*)(sU + U_QSZ + e * U_STRIDE + hv * 4) = st;
                    }
                }
                __syncthreads();

                // ---- mma phase: warp owns ONE q; A ldmatrix, B direct LDG ----
                if (qq < nqc) {
                    const __half* bq =
                        bBase + (qb + qq) * 4096 + hlf * 2048;
#pragma unroll
                    for (int ks = 0; ks < 2; ++ks) {
                        uint32_t aF0[4], aF1[4];
                        ldmx4(aF0, aFragBase + ks * 32);            // rows 0-15
                        ldmx4(aF1, aFragBase + ks * 32 + 16 * 80);  // rows 16-31
#pragma unroll
                        for (int nt = 0; nt < 4; ++nt) {
                            uint2 b = __ldg(
                                (const uint2*)(bq + nt * 256 + ks * 16));
                            mma16(acc[0][nt], aF0, b.x, b.y);
                            mma16(acc[1][nt], aF1, b.x, b.y);
                        }
                    }
                }
                __syncthreads();
            }
        }
    }

    // ---- cross-q reduction: qq=1 warps dump acc, qq=0 warps add ----
    {
        float* sRed = (float*)smx;   // 4 tiles x 32x32 f32 = 16KB (sSrc dead)
        float* tile = sRed + (wy2 * 2 + wx) * 1024;
        if (qq == 1) {
#pragma unroll
            for (int mt = 0; mt < 2; ++mt)
#pragma unroll
                for (int nt = 0; nt < 4; ++nt)
#pragma unroll
                    for (int r = 0; r < 4; ++r) {
                        int row = mt * 16 + gid + (r >> 1) * 8;
                        int col = nt * 8 + tig * 2 + (r & 1);
                        tile[row * 32 + col] = acc[mt][nt][r];
                    }
        }
        __syncthreads();
        if (qq == 0) {
#pragma unroll
            for (int mt = 0; mt < 2; ++mt)
#pragma unroll
                for (int nt = 0; nt < 4; ++nt)
#pragma unroll
                    for (int r = 0; r < 4; ++r) {
                        int row = mt * 16 + gid + (r >> 1) * 8;
                        int col = nt * 8 + tig * 2 + (r & 1);
                        acc[mt][nt][r] += tile[row * 32 + col];
                    }
            // ---- epilogue: float2 atomics into out[dst] ----
#pragma unroll
            for (int mt = 0; mt < 2; ++mt)
#pragma unroll
                for (int r = 0; r < 2; ++r) {
                    int e = wy2 * 32 + mt * 16 + gid + r * 8;
                    int dst = sIdx[EPB + e];
                    if (dst >= 0) {
                        float* op = out + (size_t)dst * 64 + wx * 32 + 2 * tig;
#pragma unroll
                        for (int nt = 0; nt < 4; ++nt) {
                            float2 v = make_float2(acc[mt][nt][r * 2],
                                                   acc[mt][nt][r * 2 + 1]);
                            atomicAdd((float2*)(op + nt * 8), v);
                        }
                    }
                }
        }
    }
}

// ---------------------------------------------------------------------------
extern "C" void kernel_launch(void* const* d_in, const int* in_sizes, int n_in,
                              void* d_out, int out_size) {
    const float* nf = (const float*)d_in[0];
    const float* ev = (const float*)d_in[1];
    const int* ei = (const int*)d_in[2];
    const float* cg = (const float*)d_in[3];
    const float* tw = (const float*)d_in[4];
    const float* wlin = (const float*)d_in[5];
    const float* bl = (const float*)d_in[6];
    float* out = (float*)d_out;
    const int E = in_sizes[1] / 3;
    const int N = in_sizes[0] / 1024;

    cudaFuncSetAttribute(edge_kernel,
                         cudaFuncAttributeMaxDynamicSharedMemorySize, SMEM_TOTAL);
    build_M_kernel<<<Q_TOTAL, 256>>>(tw, wlin);
    init_out_kernel<<<(N * 64 + 255) / 256, 256>>>(out, bl, N * 64);
    edge_kernel<<<(E + EPB - 1) / EPB, NTHREADS, SMEM_TOTAL>>>(nf, ev, ei, cg, out, E);
}

// round 16
// speedup vs baseline: 1.2980x; 1.1298x over previous
#include <cuda_runtime.h>
#include <cuda_fp16.h>
#include <cstdint>

// ============================================================================
// SimpleMACELayer — Round 15: R14 + phase-B U-production in packed half2
// (HFMA2). EPB=64, q-split warps, ldmatrix A-frags, direct-LDG B-frags,
// fp16 mma.sync m16n8k16, 4 CTAs/SM.
// ============================================================================

#define EPB 64
#define NTHREADS 256
#define Q_TOTAL 99

__constant__ signed char cQP[Q_TOTAL] = {
    0, 1,1,1, 2,2,2,2,2, 3,3,3,3,3,3,3,
    4,4,4, 5, 6,6,6,6,6, 7,7,7, 8,8,8,8,8,8,8, 9,9,9,9,9,
    10,10,10,10,10, 11,11,11, 12,12,12,12,12,12,12, 13,
    14,14,14,14,14, 15,15,15, 16,16,16,16,16,16,16,
    17,17,17,17,17,17,17, 18,18,18,18,18, 19,19,19,
    20,20,20,20,20,20,20, 21, 22,22,22,22,22};
__constant__ signed char cQKG[Q_TOTAL] = {
    0, 1,2,3, 4,5,6,7,8, 9,10,11,12,13,14,15,
    1,2,3, 0, 4,5,6,7,8, 1,2,3, 9,10,11,12,13,14,15, 4,5,6,7,8,
    4,5,6,7,8, 1,2,3, 9,10,11,12,13,14,15, 0,
    4,5,6,7,8, 1,2,3, 9,10,11,12,13,14,15,
    9,10,11,12,13,14,15, 4,5,6,7,8, 1,2,3,
    9,10,11,12,13,14,15, 0, 4,5,6,7,8};
__constant__ signed char cQJ0[Q_TOTAL] = {
    0, 1,1,1, 4,4,4,4,4, 9,9,9,9,9,9,9,
    0,0,0, 1, 1,1,1,1,1, 4,4,4, 4,4,4,4,4,4,4, 9,9,9,9,9,
    0,0,0,0,0, 1,1,1, 1,1,1,1,1,1,1, 4,
    4,4,4,4,4, 9,9,9, 9,9,9,9,9,9,9,
    0,0,0,0,0,0,0, 1,1,1,1,1, 4,4,4,
    4,4,4,4,4,4,4, 9, 9,9,9,9,9};
__constant__ int cPSTART[5] = {0, 16, 40, 71, 99};

// Fused weights, fp16, B-fragment-permuted and hlf-major:
// g_Mb[q*4096 + hlf*2048 + o'*32 + ks*16 + slot]; lane tig reads slots
// [tig*4..tig*4+3] = (k0,k0+1,k0+8,k0+9) = (b0,b1) as one LDG.64.
__device__ __half g_Mb[Q_TOTAL * 4096];

__device__ __forceinline__ void mma16(float* c, const uint32_t* a,
                                      uint32_t b0, uint32_t b1) {
    asm volatile(
        "mma.sync.aligned.m16n8k16.row.col.f32.f16.f16.f32 "
        "{%0,%1,%2,%3}, {%4,%5,%6,%7}, {%8,%9}, {%0,%1,%2,%3};"
        : "+f"(c[0]), "+f"(c[1]), "+f"(c[2]), "+f"(c[3])
        : "r"(a[0]), "r"(a[1]), "r"(a[2]), "r"(a[3]), "r"(b0), "r"(b1));
}
__device__ __forceinline__ void ldmx4(uint32_t* r, uint32_t addr) {
    asm volatile(
        "ldmatrix.sync.aligned.m8n8.x4.shared.b16 {%0,%1,%2,%3}, [%4];"
        : "=r"(r[0]), "=r"(r[1]), "=r"(r[2]), "=r"(r[3]) : "r"(addr));
}
__device__ __forceinline__ uint32_t smem_u32(const void* p) {
    uint32_t a;
    asm("{ .reg .u64 t; cvta.to.shared.u64 t, %1; cvt.u32.u64 %0, t; }"
        : "=r"(a) : "l"(p));
    return a;
}

// ---------------------------------------------------------------------------
__global__ void build_M_kernel(const float* __restrict__ tw,
                               const float* __restrict__ wlin) {
    int q = blockIdx.x, p = cQP[q], kg = cQKG[q];
    __shared__ float twS[4096], wlS[4096];
    for (int i = threadIdx.x; i < 4096; i += blockDim.x) twS[i] = tw[p * 4096 + i];
    for (int i = threadIdx.x; i < 4096; i += blockDim.x) {
        int o = i >> 6, op = i & 63;
        wlS[o * 64 + op] = wlin[op * 1024 + o * 16 + kg];
    }
    __syncthreads();
    for (int r = threadIdx.x; r < 4096; r += blockDim.x) {
        int h = r >> 6, op = r & 63;
        float acc = 0.0f;
#pragma unroll 8
        for (int o = 0; o < 64; ++o) acc += twS[h * 64 + o] * wlS[o * 64 + op];
        int hlf = h >> 5, rr = h & 31;
        int ks = rr >> 4, r16 = rr & 15;
        int slot = (r16 < 8) ? ((r16 >> 1) * 4 + (r16 & 1))
                             : (((r16 & 7) >> 1) * 4 + 2 + (r16 & 1));
        g_Mb[q * 4096 + hlf * 2048 + op * 32 + ks * 16 + slot] =
            __float2half_rn(acc);
    }
}

__global__ void init_out_kernel(float* __restrict__ out,
                                const float* __restrict__ b, int total) {
    int i = blockIdx.x * blockDim.x + threadIdx.x;
    if (i < total) out[i] = b[i & 63];
}

// ---------------------------------------------------------------------------
// SMEM layout (bytes), EPB=64:
//   sSrc half  [ic7][e64][hh32]        0     28672  (reused as sRed 16KB)
//   sU   half  [q2][e64][40]       28672     10240  (row 80B)
//   sY   f32   [j16][e64]          38912      4096
//   sAh  half2 [ic7][e64]          43008      1792
//   sIdx i32   [2][64]             44800       512
// total 45312 B -> 4 CTAs/SM
#define U_OFF   28672
#define Y_OFF   38912
#define A_OFF   43008
#define IDX_OFF 44800
#define SMEM_TOTAL 45312

#define U_STRIDE 40
#define U_QSZ (EPB * U_STRIDE)   // 2560 halves = 5120 B

__global__ __launch_bounds__(NTHREADS, 4)
void edge_kernel(const float* __restrict__ nf, const float* __restrict__ ev,
                 const int* __restrict__ ei, const float* __restrict__ cg,
                 float* __restrict__ out, int E) {
    extern __shared__ char smx[];
    __half* sSrc = (__half*)smx;
    __half* sU = (__half*)(smx + U_OFF);
    float* sY = (float*)(smx + Y_OFF);
    __half2* sAh = (__half2*)(smx + A_OFF);   // packed (a_q0, a_q1)
    int* sIdx = (int*)(smx + IDX_OFF);
    const int tid = threadIdx.x;
    const int e0 = blockIdx.x * EPB;
    const uint32_t sb = smem_u32(smx);

    // ---- Y + indices ----
    if (tid < EPB) {
        int e = e0 + tid;
        if (e < E) {
            float x = ev[e * 3], y = ev[e * 3 + 1], z = ev[e * 3 + 2];
            float x2 = x * x, y2 = y * y, z2 = z * z;
            float Y[16];
            Y[0] = 0.28209479177387814f;
            Y[1] = 0.4886025119029199f * y;
            Y[2] = 0.4886025119029199f * z;
            Y[3] = 0.4886025119029199f * x;
            Y[4] = 1.0925484305920792f * x * y;
            Y[5] = 1.0925484305920792f * y * z;
            Y[6] = 0.31539156525252005f * (3.0f * z2 - 1.0f);
            Y[7] = 1.0925484305920792f * x * z;
            Y[8] = 0.5462742152960396f * (x2 - y2);
            Y[9] = 0.5900435899266435f * y * (3.0f * x2 - y2);
            Y[10] = 2.890611442640554f * x * y * z;
            Y[11] = 0.4570457994644658f * y * (5.0f * z2 - 1.0f);
            Y[12] = 0.3731763325901154f * z * (5.0f * z2 - 3.0f);
            Y[13] = 0.4570457994644658f * x * (5.0f * z2 - 1.0f);
            Y[14] = 1.445305721320277f * z * (x2 - y2);
            Y[15] = 0.5900435899266435f * x * (x2 - 3.0f * y2);
#pragma unroll
            for (int j = 0; j < 16; ++j) sY[j * EPB + tid] = Y[j];
            sIdx[tid] = ei[e];
            sIdx[EPB + tid] = ei[E + e];
        } else {
#pragma unroll
            for (int j = 0; j < 16; ++j) sY[j * EPB + tid] = 0.0f;
            sIdx[tid] = 0;
            sIdx[EPB + tid] = -1;
        }
    }

    // q-split warp mapping: warp = (qq, wx, wy2)
    const int lane = tid & 31, gid = lane >> 2, tig = lane & 3;
    const int wid = tid >> 5;
    const int qq = wid & 1;
    const int wx = (wid >> 1) & 1;
    const int wy2 = wid >> 2;
    float acc[2][4][4];
#pragma unroll
    for (int mt = 0; mt < 2; ++mt)
#pragma unroll
        for (int nt = 0; nt < 4; ++nt)
#pragma unroll
            for (int r = 0; r < 4; ++r) acc[mt][nt][r] = 0.0f;

    const uint32_t aFragBase = sb + U_OFF + qq * 5120 +
        (uint32_t)((wy2 * 32 + (lane & 15)) * 80 + (lane >> 4) * 16);
    const __half* bBase = g_Mb + (wx * 32 + gid) * 32 + tig * 4;
    __syncthreads();

    for (int g = 0; g < 4; ++g) {
        const int nc = 2 * g + 1, i0 = g * g;
        for (int hlf = 0; hlf < 2; ++hlf) {
            // ---- gather sSrc[ic][e][hh] (vectorized over irreps) ----
            for (int idx = tid; idx < EPB * 32; idx += NTHREADS) {
                int e = idx >> 5, hh = idx & 31;
                const float* base =
                    nf + (size_t)sIdx[e] * 1024 + (hlf * 32 + hh) * 16;
                __half* d = sSrc + e * 32 + hh;  // + ic*2048
                if (g == 0) {
                    d[0] = __float2half_rn(__ldg(base));
                } else if (g == 1) {
                    float4 v = __ldg((const float4*)base);
                    d[0] = __float2half_rn(v.y);
                    d[2048] = __float2half_rn(v.z);
                    d[4096] = __float2half_rn(v.w);
                } else if (g == 2) {
                    float4 v = __ldg((const float4*)(base + 4));
                    float s = __ldg(base + 8);
                    d[0] = __float2half_rn(v.x);
                    d[2048] = __float2half_rn(v.y);
                    d[4096] = __float2half_rn(v.z);
                    d[6144] = __float2half_rn(v.w);
                    d[8192] = __float2half_rn(s);
                } else {
                    float4 va = __ldg((const float4*)(base + 8));
                    float4 vb = __ldg((const float4*)(base + 12));
                    d[0] = __float2half_rn(va.y);
                    d[2048] = __float2half_rn(va.z);
                    d[4096] = __float2half_rn(va.w);
                    d[6144] = __float2half_rn(vb.x);
                    d[8192] = __float2half_rn(vb.y);
                    d[10240] = __float2half_rn(vb.z);
                    d[12288] = __float2half_rn(vb.w);
                }
            }
            __syncthreads();

            const int qend = cPSTART[g + 1];
            for (int qb = cPSTART[g]; qb < qend; qb += 2) {
                const int nqc = (qend - qb >= 2) ? 2 : 1;

                // ---- phase A: A-coeffs -> packed half2 sAh ----
                for (int idx = tid; idx < nc * EPB; idx += NTHREADS) {
                    int e = idx & 63, ic = idx >> 6;
                    float a01[2];
                    a01[1] = 0.0f;
                    for (int qi = 0; qi < nqc; ++qi) {
                        int q = qb + qi;
                        int j0 = cQJ0[q], kg = cQKG[q];
                        int nj = (j0 == 0) ? 1 : (j0 == 1) ? 3 : (j0 == 4) ? 5 : 7;
                        const float* cgp = cg + (i0 + ic) * 256 + j0 * 16 + kg;
                        float a = 0.0f;
#pragma unroll
                        for (int jc = 0; jc < 7; ++jc)
                            if (jc < nj)
                                a += sY[(j0 + jc) * EPB + e] * __ldg(cgp + jc * 16);
                        a01[qi] = a;
                    }
                    sAh[ic * EPB + e] = __floats2half2_rn(a01[0], a01[1]);
                }
                __syncthreads();

                // ---- phase B: U tiles in packed half2 (HFMA2) ----
                for (int idx = tid; idx < EPB * 8; idx += NTHREADS) {
                    int e = idx >> 3, hv = idx & 7;
                    __half2 u00 = __float2half2_rn(0.f), u01 = u00;
                    __half2 u10 = u00, u11 = u00;
#pragma unroll
                    for (int ic = 0; ic < 7; ++ic)
                        if (ic < nc) {
                            uint2 sw = *(const uint2*)(sSrc + ic * 2048 +
                                                       e * 32 + hv * 4);
                            __half2 s0 = *(__half2*)&sw.x;
                            __half2 s1 = *(__half2*)&sw.y;
                            __half2 a2 = sAh[ic * EPB + e];
                            __half2 a0 = __half2half2(__low2half(a2));
                            u00 = __hfma2(a0, s0, u00);
                            u01 = __hfma2(a0, s1, u01);
                            if (nqc == 2) {
                                __half2 a1 = __half2half2(__high2half(a2));
                                u10 = __hfma2(a1, s0, u10);
                                u11 = __hfma2(a1, s1, u11);
                            }
                        }
                    {
                        uint2 st = {*(uint32_t*)&u00, *(uint32_t*)&u01};
                        *(uint2*)(sU + e * U_STRIDE + hv * 4) = st;
                    }
                    if (nqc == 2) {
                        uint2 st = {*(uint32_t*)&u10, *(uint32_t*)&u11};
                        *(uint2*)(sU + U_QSZ + e * U_STRIDE + hv * 4) = st;
                    }
                }
                __syncthreads();

                // ---- mma phase: warp owns ONE q; A ldmatrix, B direct LDG ----
                if (qq < nqc) {
                    const __half* bq = bBase + (qb + qq) * 4096 + hlf * 2048;
#pragma unroll
                    for (int ks = 0; ks < 2; ++ks) {
                        uint32_t aF0[4], aF1[4];
                        ldmx4(aF0, aFragBase + ks * 32);
                        ldmx4(aF1, aFragBase + ks * 32 + 16 * 80);
#pragma unroll
                        for (int nt = 0; nt < 4; ++nt) {
                            uint2 b = __ldg(
                                (const uint2*)(bq + nt * 256 + ks * 16));
                            mma16(acc[0][nt], aF0, b.x, b.y);
                            mma16(acc[1][nt], aF1, b.x, b.y);
                        }
                    }
                }
                __syncthreads();
            }
        }
    }

    // ---- cross-q reduction + epilogue ----
    {
        float* sRed = (float*)smx;
        float* tile = sRed + (wy2 * 2 + wx) * 1024;
        if (qq == 1) {
#pragma unroll
            for (int mt = 0; mt < 2; ++mt)
#pragma unroll
                for (int nt = 0; nt < 4; ++nt)
#pragma unroll
                    for (int r = 0; r < 4; ++r) {
                        int row = mt * 16 + gid + (r >> 1) * 8;
                        int col = nt * 8 + tig * 2 + (r & 1);
                        tile[row * 32 + col] = acc[mt][nt][r];
                    }
        }
        __syncthreads();
        if (qq == 0) {
#pragma unroll
            for (int mt = 0; mt < 2; ++mt)
#pragma unroll
                for (int nt = 0; nt < 4; ++nt)
#pragma unroll
                    for (int r = 0; r < 4; ++r) {
                        int row = mt * 16 + gid + (r >> 1) * 8;
                        int col = nt * 8 + tig * 2 + (r & 1);
                        acc[mt][nt][r] += tile[row * 32 + col];
                    }
#pragma unroll
            for (int mt = 0; mt < 2; ++mt)
#pragma unroll
                for (int r = 0; r < 2; ++r) {
                    int e = wy2 * 32 + mt * 16 + gid + r * 8;
                    int dst = sIdx[EPB + e];
                    if (dst >= 0) {
                        float* op = out + (size_t)dst * 64 + wx * 32 + 2 * tig;
#pragma unroll
                        for (int nt = 0; nt < 4; ++nt) {
                            float2 v = make_float2(acc[mt][nt][r * 2],
                                                   acc[mt][nt][r * 2 + 1]);
                            atomicAdd((float2*)(op + nt * 8), v);
                        }
                    }
                }
        }
    }
}

// ---------------------------------------------------------------------------
extern "C" void kernel_launch(void* const* d_in, const int* in_sizes, int n_in,
                              void* d_out, int out_size) {
    const float* nf = (const float*)d_in[0];
    const float* ev = (const float*)d_in[1];
    const int* ei = (const int*)d_in[2];
    const float* cg = (const float*)d_in[3];
    const float* tw = (const float*)d_in[4];
    const float* wlin = (const float*)d_in[5];
    const float* bl = (const float*)d_in[6];
    float* out = (float*)d_out;
    const int E = in_sizes[1] / 3;
    const int N = in_sizes[0] / 1024;

    cudaFuncSetAttribute(edge_kernel,
                         cudaFuncAttributeMaxDynamicSharedMemorySize, SMEM_TOTAL);
    build_M_kernel<<<Q_TOTAL, 256>>>(tw, wlin);
    init_out_kernel<<<(N * 64 + 255) / 256, 256>>>(out, bl, N * 64);
    edge_kernel<<<(E + EPB - 1) / EPB, NTHREADS, SMEM_TOTAL>>>(nf, ev, ei, cg, out, E);
}